// round 7
// baseline (speedup 1.0000x reference)
#include <cuda_runtime.h>
#include <cuda_bf16.h>

// Problem dims (fixed by reference setup_inputs)
#define B_   4
#define N_   32
#define R_   64
#define H_   480
#define W_   640
#define HW_  (H_ * W_)         // 307200
#define NVEC (HW_ / 4)         // 76800 float4 per (b,n) slice
#define BN_  (B_ * N_)         // 128
#define BR_  (B_ * R_)         // 256

#define NGRP    8              // n-values per block
#define GROUPS  (B_ * N_ / NGRP)   // 16
#define CHUNKS  37             // 16*37 = 592 = 4*148 blocks, one balanced wave
#define NBLOCKS (GROUPS * CHUNKS)
#define CHUNK_SZ ((NVEC + CHUNKS - 1) / CHUNKS)   // 2076

#define MARGIN_RANK 0.1f
#define MARGIN_OCC  0.3f
#define LAMBDA_OCC  1.5f
#define MIN_PIXELS  20.0f

// Per-(chunk, bn) partials — each block owns its slots, no atomics needed.
__device__ float g_ps[CHUNKS * BN_];
__device__ float g_pc[CHUNKS * BN_];
__device__ unsigned int g_ctr = 0;   // last-block-done counter (self-resetting)

__global__ void __launch_bounds__(256) fused_kernel(
    const float* __restrict__ depth,   // [B,1,H,W]
    const float* __restrict__ masks,   // [B,N,H,W]
    const int*   __restrict__ subj,
    const int*   __restrict__ obj,
    const int*   __restrict__ rel,
    const float* __restrict__ conf,
    float*       __restrict__ out)
{
    const int bx    = blockIdx.x;          // 0..591
    const int chunk = bx % CHUNKS;
    const int grp   = bx / CHUNKS;         // 0..15
    const int b     = grp >> 2;            // 4 groups per batch
    const int n0    = (grp & 3) * NGRP;

    const float4* __restrict__ dp = reinterpret_cast<const float4*>(depth)
                                    + (size_t)b * NVEC;
    const float4* __restrict__ mp = reinterpret_cast<const float4*>(masks)
                                    + (size_t)(b * N_ + n0) * NVEC;

    float s[NGRP], c[NGRP];
    #pragma unroll
    for (int j = 0; j < NGRP; ++j) { s[j] = 0.0f; c[j] = 0.0f; }

    const int i0 = chunk * CHUNK_SZ;
    const int i1 = min(i0 + CHUNK_SZ, NVEC);

    for (int i = i0 + threadIdx.x; i < i1; i += 256) {
        float4 d = dp[i];
        float4 m[NGRP];
        #pragma unroll
        for (int j = 0; j < NGRP; ++j)
            m[j] = mp[(size_t)j * NVEC + i];
        #pragma unroll
        for (int j = 0; j < NGRP; ++j) {
            if (m[j].x > 0.5f) { s[j] += d.x; c[j] += 1.0f; }
            if (m[j].y > 0.5f) { s[j] += d.y; c[j] += 1.0f; }
            if (m[j].z > 0.5f) { s[j] += d.z; c[j] += 1.0f; }
            if (m[j].w > 0.5f) { s[j] += d.w; c[j] += 1.0f; }
        }
    }

    // Warp-reduce all 16 accumulators
    #pragma unroll
    for (int j = 0; j < NGRP; ++j) {
        #pragma unroll
        for (int off = 16; off > 0; off >>= 1) {
            s[j] += __shfl_xor_sync(0xFFFFFFFFu, s[j], off);
            c[j] += __shfl_xor_sync(0xFFFFFFFFu, c[j], off);
        }
    }

    __shared__ float sh[8][2 * NGRP];      // [warp][16 values]
    const int lane = threadIdx.x & 31;
    const int wid  = threadIdx.x >> 5;
    if (lane == 0) {
        #pragma unroll
        for (int j = 0; j < NGRP; ++j) {
            sh[wid][j]        = s[j];
            sh[wid][NGRP + j] = c[j];
        }
    }
    __syncthreads();

    if (threadIdx.x < 2 * NGRP) {
        float v = 0.0f;
        #pragma unroll
        for (int w = 0; w < 8; ++w) v += sh[w][threadIdx.x];
        const int j  = threadIdx.x & (NGRP - 1);
        const int bn = b * N_ + n0 + j;
        if (threadIdx.x < NGRP) g_ps[chunk * BN_ + bn] = v;
        else                    g_pc[chunk * BN_ + bn] = v;
    }

    // ---- last-block-done: the final block runs the epilogue ----
    __shared__ bool is_last;
    __threadfence();                       // make partials visible chip-wide
    __syncthreads();                       // all partial stores issued
    if (threadIdx.x == 0) {
        unsigned int prev = atomicAdd(&g_ctr, 1u);
        is_last = (prev == NBLOCKS - 1);
    }
    __syncthreads();
    if (!is_last) return;
    __threadfence();                       // acquire: order partial loads after counter

    // ===================== epilogue (one block, 256 threads) =====================
    __shared__ float sh_mean[BN_], sh_cnt[BN_];
    const int t = threadIdx.x;             // 0..255

    if (t < BN_) {
        float sAcc = 0.0f, cAcc = 0.0f;
        #pragma unroll
        for (int ch = 0; ch < CHUNKS; ++ch) {
            sAcc += g_ps[ch * BN_ + t];
            cAcc += g_pc[ch * BN_ + t];
        }
        sh_mean[t] = sAcc / fmaxf(cAcc, 1.0f);
        sh_cnt[t]  = cAcc;
    }
    __syncthreads();

    const int bb_ = t / R_;
    const int rt = rel[t];
    const int si = subj[t];
    const int oi = obj[t];
    const int a  = (rt == 1) ? oi : si;
    const int bo = (rt == 1) ? si : oi;

    const float cntA = sh_cnt[bb_ * N_ + a];
    const float cntB = sh_cnt[bb_ * N_ + bo];
    const float dA   = sh_mean[bb_ * N_ + a];
    const float dB   = sh_mean[bb_ * N_ + bo];
    const bool  valid = (cntA >= MIN_PIXELS) && (cntB >= MIN_PIXELS);

    const float margin = (rt == 2) ? MARGIN_OCC : MARGIN_RANK;
    const float coeff  = (rt == 2) ? LAMBDA_OCC : 1.0f;
    const float viol   = fmaxf(dA - dB + margin, 0.0f);

    float total = coeff * conf[t] * (valid ? 1.0f : 0.0f) * viol;
    float count = valid ? 1.0f : 0.0f;

    #pragma unroll
    for (int off = 16; off > 0; off >>= 1) {
        total += __shfl_xor_sync(0xFFFFFFFFu, total, off);
        count += __shfl_xor_sync(0xFFFFFFFFu, count, off);
    }
    __shared__ float sh_t[8], sh_n[8];
    if (lane == 0) { sh_t[wid] = total; sh_n[wid] = count; }
    __syncthreads();
    if (t == 0) {
        float T = 0.0f, C = 0.0f;
        #pragma unroll
        for (int w = 0; w < 8; ++w) { T += sh_t[w]; C += sh_n[w]; }
        out[0] = (C > 0.0f) ? (T / fmaxf(C, 1.0f)) : 0.0f;
        g_ctr = 0;                        // reset for next graph replay
    }
}

extern "C" void kernel_launch(void* const* d_in, const int* in_sizes, int n_in,
                              void* d_out, int out_size)
{
    const float* depth = (const float*)d_in[0];
    const float* masks = (const float*)d_in[1];
    const int*   subj  = (const int*)  d_in[2];
    const int*   obj   = (const int*)  d_in[3];
    const int*   rel   = (const int*)  d_in[4];
    const float* conf  = (const float*)d_in[5];
    float*       out   = (float*)d_out;

    fused_kernel<<<NBLOCKS, 256>>>(depth, masks, subj, obj, rel, conf, out);
}

// round 8
// speedup vs baseline: 1.0411x; 1.0411x over previous
#include <cuda_runtime.h>
#include <cuda_bf16.h>
#include <cstdint>

// Problem dims (fixed by reference setup_inputs)
#define B_   4
#define N_   32
#define R_   64
#define H_   480
#define W_   640
#define HW_  (H_ * W_)         // 307200
#define NVEC (HW_ / 4)         // 76800 float4 per (b,n) slice
#define BN_  (B_ * N_)         // 128
#define BR_  (B_ * R_)         // 256

#define NGRP    8                    // n-values per block
#define GROUPS  (B_ * N_ / NGRP)     // 16
#define CHUNKS  37                   // 16*37 = 592 = 4*148 blocks, one balanced wave
#define NBLOCKS (GROUPS * CHUNKS)

#define T_F4        128              // float4 per array per tile (2KB)
#define NARR        (NGRP + 1)       // 8 masks + 1 depth
#define STAGES      2
#define TILES_GRP   (NVEC / T_F4)    // 600 tiles per (b,n) group

#define MARGIN_RANK 0.1f
#define MARGIN_OCC  0.3f
#define LAMBDA_OCC  1.5f
#define MIN_PIXELS  20.0f

// Per-(chunk, bn) partials — each block owns its slots, no atomics needed.
__device__ float g_ps[CHUNKS * BN_];
__device__ float g_pc[CHUNKS * BN_];
__device__ unsigned int g_ctr = 0;   // last-block-done counter (self-resetting)

__device__ __forceinline__ uint32_t smem_u32(const void* p) {
    return (uint32_t)__cvta_generic_to_shared(p);
}
__device__ __forceinline__ void cp_async16(uint32_t dst, const void* src) {
    asm volatile("cp.async.cg.shared.global [%0], [%1], 16;\n" :: "r"(dst), "l"(src));
}
#define CP_COMMIT() asm volatile("cp.async.commit_group;\n" ::: "memory")
#define CP_WAIT(n)  asm volatile("cp.async.wait_group %0;\n" :: "n"(n) : "memory")

__global__ void __launch_bounds__(256) fused_kernel(
    const float* __restrict__ depth,   // [B,1,H,W]
    const float* __restrict__ masks,   // [B,N,H,W]
    const int*   __restrict__ subj,
    const int*   __restrict__ obj,
    const int*   __restrict__ rel,
    const float* __restrict__ conf,
    float*       __restrict__ out)
{
    // Pipeline smem: [stage][array][T_F4] float4; array 0..7 = masks, 8 = depth
    __shared__ float4 tile[STAGES * NARR * T_F4];    // 36 KB

    const int tid   = threadIdx.x;
    const int bx    = blockIdx.x;          // 0..591
    const int chunk = bx % CHUNKS;
    const int grp   = bx / CHUNKS;         // 0..15
    const int b     = grp >> 2;            // 4 groups per batch
    const int n0    = (grp & 3) * NGRP;

    const float4* __restrict__ dp = reinterpret_cast<const float4*>(depth)
                                    + (size_t)b * NVEC;
    const float4* __restrict__ mp = reinterpret_cast<const float4*>(masks)
                                    + (size_t)(b * N_ + n0) * NVEC;

    // Tile range for this chunk (whole tiles; 600 split over 37 chunks)
    const int t0 = (chunk * TILES_GRP) / CHUNKS;
    const int t1 = ((chunk + 1) * TILES_GRP) / CHUNKS;
    const int nt = t1 - t0;

    float s[NGRP], c[NGRP];
    #pragma unroll
    for (int j = 0; j < NGRP; ++j) { s[j] = 0.0f; c[j] = 0.0f; }

    // ---- async copy of one tile into a stage ----
    auto issue = [&](int stage, int t) {
        const size_t goff = (size_t)t * T_F4;
        uint32_t base = smem_u32(&tile[stage * NARR * T_F4]);
        #pragma unroll
        for (int idx = 0; idx < NARR * T_F4; idx += 256) {
            int k = idx + tid;
            if (k < NARR * T_F4) {
                int a = k >> 7;               // k / T_F4
                int e = k & (T_F4 - 1);
                const float4* src = (a < NGRP) ? (mp + (size_t)a * NVEC + goff + e)
                                               : (dp + goff + e);
                cp_async16(base + (uint32_t)k * 16u, src);
            }
        }
    };

    // Prologue
    #pragma unroll
    for (int k = 0; k < STAGES; ++k) {
        if (k < nt) issue(k, t0 + k);
        CP_COMMIT();
    }

    // Main pipeline
    for (int k = 0; k < nt; ++k) {
        const int st = k & (STAGES - 1);
        CP_WAIT(STAGES - 1);
        __syncthreads();

        // Consume: each thread owns float2 lane tid of the 512-float tile
        const float2* dt2 = reinterpret_cast<const float2*>(&tile[(st * NARR + NGRP) * T_F4]);
        const float2  d   = dt2[tid];
        #pragma unroll
        for (int j = 0; j < NGRP; ++j) {
            const float2* mt2 = reinterpret_cast<const float2*>(&tile[(st * NARR + j) * T_F4]);
            float2 m = mt2[tid];
            if (m.x > 0.5f) { s[j] += d.x; c[j] += 1.0f; }
            if (m.y > 0.5f) { s[j] += d.y; c[j] += 1.0f; }
        }
        __syncthreads();

        if (k + STAGES < nt) issue(st, t0 + k + STAGES);
        CP_COMMIT();
    }

    // ---- reduce the 16 accumulators across the block ----
    #pragma unroll
    for (int j = 0; j < NGRP; ++j) {
        #pragma unroll
        for (int off = 16; off > 0; off >>= 1) {
            s[j] += __shfl_xor_sync(0xFFFFFFFFu, s[j], off);
            c[j] += __shfl_xor_sync(0xFFFFFFFFu, c[j], off);
        }
    }

    __shared__ float sh[8][2 * NGRP];      // [warp][16 values]
    const int lane = tid & 31;
    const int wid  = tid >> 5;
    if (lane == 0) {
        #pragma unroll
        for (int j = 0; j < NGRP; ++j) {
            sh[wid][j]        = s[j];
            sh[wid][NGRP + j] = c[j];
        }
    }
    __syncthreads();

    if (tid < 2 * NGRP) {
        float v = 0.0f;
        #pragma unroll
        for (int w = 0; w < 8; ++w) v += sh[w][tid];
        const int j  = tid & (NGRP - 1);
        const int bn = b * N_ + n0 + j;
        if (tid < NGRP) g_ps[chunk * BN_ + bn] = v;
        else            g_pc[chunk * BN_ + bn] = v;
    }

    // ---- last-block-done: the final block runs the epilogue ----
    __shared__ bool is_last;
    __threadfence();
    __syncthreads();
    if (tid == 0) {
        unsigned int prev = atomicAdd(&g_ctr, 1u);
        is_last = (prev == NBLOCKS - 1);
    }
    __syncthreads();
    if (!is_last) return;
    __threadfence();

    // ===================== epilogue (one block, 256 threads) =====================
    __shared__ float sh_mean[BN_], sh_cnt[BN_];
    if (tid < BN_) {
        float sAcc = 0.0f, cAcc = 0.0f;
        #pragma unroll
        for (int ch = 0; ch < CHUNKS; ++ch) {
            sAcc += g_ps[ch * BN_ + tid];
            cAcc += g_pc[ch * BN_ + tid];
        }
        sh_mean[tid] = sAcc / fmaxf(cAcc, 1.0f);
        sh_cnt[tid]  = cAcc;
    }
    __syncthreads();

    const int bb_ = tid / R_;
    const int rt = rel[tid];
    const int si = subj[tid];
    const int oi = obj[tid];
    const int a  = (rt == 1) ? oi : si;
    const int bo = (rt == 1) ? si : oi;

    const float cntA = sh_cnt[bb_ * N_ + a];
    const float cntB = sh_cnt[bb_ * N_ + bo];
    const float dA   = sh_mean[bb_ * N_ + a];
    const float dB   = sh_mean[bb_ * N_ + bo];
    const bool  valid = (cntA >= MIN_PIXELS) && (cntB >= MIN_PIXELS);

    const float margin = (rt == 2) ? MARGIN_OCC : MARGIN_RANK;
    const float coeff  = (rt == 2) ? LAMBDA_OCC : 1.0f;
    const float viol   = fmaxf(dA - dB + margin, 0.0f);

    float total = coeff * conf[tid] * (valid ? 1.0f : 0.0f) * viol;
    float count = valid ? 1.0f : 0.0f;

    #pragma unroll
    for (int off = 16; off > 0; off >>= 1) {
        total += __shfl_xor_sync(0xFFFFFFFFu, total, off);
        count += __shfl_xor_sync(0xFFFFFFFFu, count, off);
    }
    __shared__ float sh_t[8], sh_n[8];
    if (lane == 0) { sh_t[wid] = total; sh_n[wid] = count; }
    __syncthreads();
    if (tid == 0) {
        float T = 0.0f, C = 0.0f;
        #pragma unroll
        for (int w = 0; w < 8; ++w) { T += sh_t[w]; C += sh_n[w]; }
        out[0] = (C > 0.0f) ? (T / fmaxf(C, 1.0f)) : 0.0f;
        g_ctr = 0;                        // reset for next graph replay
    }
}

extern "C" void kernel_launch(void* const* d_in, const int* in_sizes, int n_in,
                              void* d_out, int out_size)
{
    const float* depth = (const float*)d_in[0];
    const float* masks = (const float*)d_in[1];
    const int*   subj  = (const int*)  d_in[2];
    const int*   obj   = (const int*)  d_in[3];
    const int*   rel   = (const int*)  d_in[4];
    const float* conf  = (const float*)d_in[5];
    float*       out   = (float*)d_out;

    fused_kernel<<<NBLOCKS, 256>>>(depth, masks, subj, obj, rel, conf, out);
}